// round 13
// baseline (speedup 1.0000x reference)
#include <cuda_runtime.h>
#include <cuda_fp16.h>
#include <cstdint>

#define NN 50000
#define NE 800000
#define D  96
#define NG 128
#define OD 10
#define CAP 96          // max in-degree bucket capacity (deg ~ Poisson(16))

// ---------------- scratch (static device globals; no allocation) ----------------
__device__ __align__(16) float  g_self[NN * D];
__device__ __align__(16) __half g_msg [NN * D];   // fp16 messages
__device__ __align__(16) __half g_hx  [NN * D];   // fp16 copy of x (layer-0 A)
__device__ __align__(16) __half g_hh0 [NN * D];   // fp16 hidden (ping)
__device__ __align__(16) __half g_hh1 [NN * D];   // fp16 hidden (pong)
__device__ int   g_deg [NN];
__device__ int   g_bkt [NN * CAP];
__device__ float g_emb [NG * D];

// ---------------- x -> fp16 conversion (once per launch) ----------------
__global__ void k_x2h(const float4* __restrict__ x4) {
    int i = blockIdx.x * blockDim.x + threadIdx.x;   // 4 floats per thread
    if (i < NN * D / 4) {
        float4 v = x4[i];
        __half2 p0 = __floats2half2_rn(v.x, v.y);
        __half2 p1 = __floats2half2_rn(v.z, v.w);
        *(uint2*)&g_hx[i * 4] = make_uint2(*(uint32_t*)&p0, *(uint32_t*)&p1);
    }
}

// ---------------- fused CSR bucket build: int4 loads, 4 independent chains ----------------
__global__ void k_bucket(const int4* __restrict__ src4, const int4* __restrict__ dst4) {
    int e = blockIdx.x * blockDim.x + threadIdx.x;
    if (e < NE / 4) {
        int4 s = src4[e];
        int4 d = dst4[e];
        int p0 = atomicAdd(&g_deg[d.x], 1);
        int p1 = atomicAdd(&g_deg[d.y], 1);
        int p2 = atomicAdd(&g_deg[d.z], 1);
        int p3 = atomicAdd(&g_deg[d.w], 1);
        if (p0 < CAP) g_bkt[(size_t)d.x * CAP + p0] = s.x;
        if (p1 < CAP) g_bkt[(size_t)d.y * CAP + p1] = s.y;
        if (p2 < CAP) g_bkt[(size_t)d.z * CAP + p2] = s.z;
        if (p3 < CAP) g_bkt[(size_t)d.w * CAP + p3] = s.w;
    }
}

// ---------------- fp16 MMA / async helpers ----------------
__device__ __forceinline__ void mma_f16(float* c,
                                        uint32_t a0, uint32_t a1, uint32_t a2, uint32_t a3,
                                        uint32_t b0, uint32_t b1) {
    asm volatile(
        "mma.sync.aligned.m16n8k16.row.col.f32.f16.f16.f32 "
        "{%0,%1,%2,%3}, {%4,%5,%6,%7}, {%8,%9}, {%0,%1,%2,%3};\n"
        : "+f"(c[0]), "+f"(c[1]), "+f"(c[2]), "+f"(c[3])
        : "r"(a0), "r"(a1), "r"(a2), "r"(a3), "r"(b0), "r"(b1));
}

__device__ __forceinline__ void cp16(uint32_t dst_smem, const void* src) {
    asm volatile("cp.async.ca.shared.global [%0], [%1], 16;\n" :: "r"(dst_smem), "l"(src));
}
__device__ __forceinline__ void cp_commit() {
    asm volatile("cp.async.commit_group;\n" ::: "memory");
}
template <int N>
__device__ __forceinline__ void cp_wait() {
    asm volatile("cp.async.wait_group %0;\n" :: "n"(N) : "memory");
}

// ---------------- persistent fused dual GEMM (fp16 tensor cores, fp32 accum) ---
// (unchanged — proven)
#define AH_STRIDE 52
#define ABUF_WORDS (128 * AH_STRIDE)                // 6656 words
#define SWH_WORDS  (48 * 96)                        // 4608 words per matrix
#define GEMM_DSMEM ((2 * ABUF_WORDS + 2 * SWH_WORDS) * 4)   // 88 KB
#define SW_XOR2(k2, n) ((n) ^ (((k2) & 3) * 8))
#define NTILES ((NN + 127) / 128)                   // 391
#define GEMM_GRID 148

__device__ __forceinline__ void stage_A(uint32_t abuf_addr, const __half* __restrict__ h,
                                        int row0, int t) {
#pragma unroll
    for (int i = 0; i < 3; i++) {
        int lin = t + i * 512;               // 0..1535
        int r = lin / 12;                    // 0..127
        int j = lin - r * 12;                // 0..11 (uint4 = 8 halves)
        int grow = row0 + r;
        if (grow >= NN) grow = NN - 1;       // clamp: masked at store
        cp16(abuf_addr + (r * AH_STRIDE + j * 4) * 4, h + (size_t)grow * D + j * 8);
    }
}

__global__ void __launch_bounds__(512, 1)
k_gemm_dual_tc(const __half* __restrict__ h,
               const float* __restrict__ W1, const float* __restrict__ W2) {
    extern __shared__ uint32_t smem[];
    uint32_t* sA = smem;                       // 2 x ABUF_WORDS (half2 words)
    uint32_t* sW = smem + 2 * ABUF_WORDS;      // 2 x [48][96] packed half2, xor-swizzled
    uint32_t sA_addr = (uint32_t)__cvta_generic_to_shared(sA);

    int t     = threadIdx.x;
    int warp  = t >> 5;
    int lane  = t & 31;
    int gq    = lane >> 2;
    int t4    = lane & 3;
    int warpM = warp >> 2;          // 0..3 -> rows [warpM*32, +32)
    int warpN = (warp >> 1) & 1;    // 0..1 -> cols [warpN*48, +48)
    int mat   = warp & 1;           // 0: W1/self, 1: W2/msg

    // ---- stage W1/W2 once: pack (k, k+1) pairs into half2, xor-swizzled ----
#pragma unroll
    for (int i = 0; i < 3; i++) {
        int idx = t + i * 512;               // 0..1535, need < 1152
        if (idx < 1152) {
            int k2 = idx / 24;               // 0..47
            int n4 = (idx - k2 * 24) * 4;    // 0..92
            const float* r0 = W1 + (2 * k2) * D + n4;
            float4 wa = *(const float4*)r0;
            float4 wb = *(const float4*)(r0 + D);
            __half2 p0 = __floats2half2_rn(wa.x, wb.x);
            __half2 p1 = __floats2half2_rn(wa.y, wb.y);
            __half2 p2 = __floats2half2_rn(wa.z, wb.z);
            __half2 p3 = __floats2half2_rn(wa.w, wb.w);
            int di = k2 * 96 + SW_XOR2(k2, n4);
            *(uint4*)&sW[di] = make_uint4(*(uint32_t*)&p0, *(uint32_t*)&p1,
                                          *(uint32_t*)&p2, *(uint32_t*)&p3);
            const float* q0 = W2 + (2 * k2) * D + n4;
            float4 va = *(const float4*)q0;
            float4 vb = *(const float4*)(q0 + D);
            __half2 u0 = __floats2half2_rn(va.x, vb.x);
            __half2 u1 = __floats2half2_rn(va.y, vb.y);
            __half2 u2 = __floats2half2_rn(va.z, vb.z);
            __half2 u3 = __floats2half2_rn(va.w, vb.w);
            *(uint4*)&sW[SWH_WORDS + di] = make_uint4(*(uint32_t*)&u0, *(uint32_t*)&u1,
                                                      *(uint32_t*)&u2, *(uint32_t*)&u3);
        }
    }

    const uint32_t* sWm = sW + mat * SWH_WORDS;

    int tile0 = blockIdx.x;
    if (tile0 >= NTILES) return;

    stage_A(sA_addr, h, tile0 * 128, t);
    cp_commit();

    int buf = 0;
    for (int tile = tile0; tile < NTILES; tile += GEMM_GRID) {
        int ntile = tile + GEMM_GRID;
        if (ntile >= NTILES) ntile = tile;
        stage_A(sA_addr + (buf ^ 1) * ABUF_WORDS * 4, h, ntile * 128, t);
        cp_commit();

        cp_wait<1>();
        __syncthreads();

        const uint32_t* A = sA + buf * ABUF_WORDS;
        float acc[2][6][4];
#pragma unroll
        for (int mt = 0; mt < 2; mt++)
#pragma unroll
            for (int nt = 0; nt < 6; nt++)
#pragma unroll
                for (int j = 0; j < 4; j++) acc[mt][nt][j] = 0.f;

#pragma unroll
        for (int ks = 0; ks < 6; ks++) {
            int k2b = ks * 8;
            uint32_t a0[2], a1[2], a2[2], a3[2];
#pragma unroll
            for (int mt = 0; mt < 2; mt++) {
                int r = warpM * 32 + mt * 16 + gq;
                int idx = r * AH_STRIDE + k2b + t4;
                a0[mt] = A[idx];
                a1[mt] = A[idx + 8 * AH_STRIDE];
                a2[mt] = A[idx + 4];
                a3[mt] = A[idx + 8 * AH_STRIDE + 4];
            }
#pragma unroll
            for (int nt = 0; nt < 6; nt++) {
                int n = warpN * 48 + nt * 8 + gq;
                int kb0 = k2b + t4;
                int kb1 = k2b + t4 + 4;
                uint32_t b0 = sWm[kb0 * 96 + SW_XOR2(kb0, n)];
                uint32_t b1 = sWm[kb1 * 96 + SW_XOR2(kb1, n)];
#pragma unroll
                for (int mt = 0; mt < 2; mt++)
                    mma_f16(acc[mt][nt], a0[mt], a1[mt], a2[mt], a3[mt], b0, b1);
            }
        }

        // epilogue: mat 0 -> g_self (fp32), mat 1 -> g_msg (fp16)
        int row0 = tile * 128;
#pragma unroll
        for (int mt = 0; mt < 2; mt++) {
            int row = row0 + warpM * 32 + mt * 16 + gq;
#pragma unroll
            for (int nt = 0; nt < 6; nt++) {
                int col = warpN * 48 + nt * 8 + 2 * t4;
                if (mat == 0) {
                    if (row < NN)
                        *(float2*)&g_self[row * D + col] = make_float2(acc[mt][nt][0], acc[mt][nt][1]);
                    if (row + 8 < NN)
                        *(float2*)&g_self[(row + 8) * D + col] = make_float2(acc[mt][nt][2], acc[mt][nt][3]);
                } else {
                    if (row < NN)
                        *(__half2*)&g_msg[row * D + col] =
                            __float22half2_rn(make_float2(acc[mt][nt][0], acc[mt][nt][1]));
                    if (row + 8 < NN)
                        *(__half2*)&g_msg[(row + 8) * D + col] =
                            __float22half2_rn(make_float2(acc[mt][nt][2], acc[mt][nt][3]));
                }
            }
        }
        __syncthreads();
        buf ^= 1;
    }
}

// ---------------- aggregation (exact R10 shape: 32 regs, occ 77.7%) ----------------
// one warp = 2 nodes (half-warp each); sublanes 0..11 own 8 dims.
// Edge pairs: fp16 HADD2 pair-sum, then fp32 accumulate.
__device__ __forceinline__ __half2 h2_(uint32_t u) { return *(__half2*)&u; }

__global__ void k_aggregate(int houtcode) {
    int gt   = blockIdx.x * blockDim.x + threadIdx.x;
    int warp = gt >> 5;
    int lane = gt & 31;
    int node = warp * 2 + (lane >> 4);
    int sub  = lane & 15;
    if (node >= NN || sub >= 12) return;

    const uint4* __restrict__ M = (const uint4*)g_msg;   // 12 uint4 per row
    float acc[8];
#pragma unroll
    for (int j = 0; j < 8; j++) acc[j] = 0.f;

    int deg = g_deg[node];
    if (deg > CAP) deg = CAP;
    const int* __restrict__ bkt = g_bkt + (size_t)node * CAP;

    int i = 0;
    for (; i + 2 <= deg; i += 2) {
        int s0 = bkt[i];
        int s1 = bkt[i + 1];
        uint4 ma = M[(size_t)s0 * 12 + sub];
        uint4 mb = M[(size_t)s1 * 12 + sub];
        __half2 p0 = __hadd2(h2_(ma.x), h2_(mb.x));
        __half2 p1 = __hadd2(h2_(ma.y), h2_(mb.y));
        __half2 p2 = __hadd2(h2_(ma.z), h2_(mb.z));
        __half2 p3 = __hadd2(h2_(ma.w), h2_(mb.w));
        float2 f0 = __half22float2(p0);
        float2 f1 = __half22float2(p1);
        float2 f2 = __half22float2(p2);
        float2 f3 = __half22float2(p3);
        acc[0] += f0.x; acc[1] += f0.y;
        acc[2] += f1.x; acc[3] += f1.y;
        acc[4] += f2.x; acc[5] += f2.y;
        acc[6] += f3.x; acc[7] += f3.y;
    }
    if (i < deg) {
        int s = bkt[i];
        uint4 mv = M[(size_t)s * 12 + sub];
        float2 f0 = __half22float2(h2_(mv.x));
        float2 f1 = __half22float2(h2_(mv.y));
        float2 f2 = __half22float2(h2_(mv.z));
        float2 f3 = __half22float2(h2_(mv.w));
        acc[0] += f0.x; acc[1] += f0.y;
        acc[2] += f1.x; acc[3] += f1.y;
        acc[4] += f2.x; acc[5] += f2.y;
        acc[6] += f3.x; acc[7] += f3.y;
    }

    const float4* __restrict__ S = (const float4*)(g_self + (size_t)node * D + sub * 8);
    float4 s0f = S[0];
    float4 s1f = S[1];
    __half* ho = ((houtcode == 0) ? g_hh0 : g_hh1) + (size_t)node * D + sub * 8;
    __half2 q0 = __floats2half2_rn(fmaxf(s0f.x + acc[0], 0.f), fmaxf(s0f.y + acc[1], 0.f));
    __half2 q1 = __floats2half2_rn(fmaxf(s0f.z + acc[2], 0.f), fmaxf(s0f.w + acc[3], 0.f));
    __half2 q2 = __floats2half2_rn(fmaxf(s1f.x + acc[4], 0.f), fmaxf(s1f.y + acc[5], 0.f));
    __half2 q3 = __floats2half2_rn(fmaxf(s1f.z + acc[6], 0.f), fmaxf(s1f.w + acc[7], 0.f));
    *(uint4*)ho = make_uint4(*(uint32_t*)&q0, *(uint32_t*)&q1,
                             *(uint32_t*)&q2, *(uint32_t*)&q3);
}

// ---------------- graph pooling (reads final fp16 h in g_hh0) ----------------
__device__ __forceinline__ int lowerb(const int* __restrict__ a, int n, int v) {
    int lo = 0, hi = n;
    while (lo < hi) {
        int mid = (lo + hi) >> 1;
        if (a[mid] < v) lo = mid + 1; else hi = mid;
    }
    return lo;
}

__global__ void k_pool(const int* __restrict__ batch) {
    __shared__ int   se[2];
    __shared__ float red[4][96];
    int g = blockIdx.x;
    int t = threadIdx.x;
    if (t == 0) se[0] = lowerb(batch, NN, g);
    if (t == 1) se[1] = lowerb(batch, NN, g + 1);
    __syncthreads();
    int d = t % 96;
    int q = t / 96;
    int s0 = se[0], s1 = se[1];
    float s = 0.f;
    for (int n = s0 + q; n < s1; n += 4) s += __half2float(g_hh0[(size_t)n * D + d]);
    red[q][d] = s;
    __syncthreads();
    if (q == 0) g_emb[g * D + d] = red[0][d] + red[1][d] + red[2][d] + red[3][d];
}

// ---------------- MLP head ----------------
__global__ void k_mlp(const float* __restrict__ cw1, const float* __restrict__ cb1,
                      const float* __restrict__ cw2, const float* __restrict__ cb2,
                      float* __restrict__ out) {
    __shared__ float emb[96];
    __shared__ float hid[96];
    int g = blockIdx.x;
    int d = threadIdx.x;  // 96 threads
    emb[d] = g_emb[g * D + d];
    __syncthreads();
    float s = cb1[d];
#pragma unroll 8
    for (int k = 0; k < 96; k++) s += emb[k] * cw1[k * D + d];
    hid[d] = fmaxf(s, 0.f);
    __syncthreads();
    if (d < OD) {
        float o = cb2[d];
#pragma unroll 8
        for (int k = 0; k < 96; k++) o += hid[k] * cw2[k * OD + d];
        out[g * OD + d] = o;
    }
}

// ---------------- launch ----------------
extern "C" void kernel_launch(void* const* d_in, const int* in_sizes, int n_in,
                              void* d_out, int out_size) {
    const float* x     = (const float*)d_in[0];
    const int*   ei    = (const int*)  d_in[1];
    const int*   batch = (const int*)  d_in[2];
    const float* W1    = (const float*)d_in[3];
    const float* W2    = (const float*)d_in[4];
    const float* cw1   = (const float*)d_in[5];
    const float* cb1   = (const float*)d_in[6];
    const float* cw2   = (const float*)d_in[7];
    const float* cb2   = (const float*)d_in[8];
    float* out = (float*)d_out;

    const int* src = ei;        // edge_index[0]
    const int* dst = ei + NE;   // edge_index[1]

    cudaFuncSetAttribute(k_gemm_dual_tc,
                         cudaFuncAttributeMaxDynamicSharedMemorySize, GEMM_DSMEM);

    void *p_deg = nullptr, *p_hx = nullptr, *p_h0 = nullptr, *p_h1 = nullptr;
    cudaGetSymbolAddress(&p_deg, g_deg);
    cudaGetSymbolAddress(&p_hx, g_hx);
    cudaGetSymbolAddress(&p_h0, g_hh0);
    cudaGetSymbolAddress(&p_h1, g_hh1);
    const __half* hx = (const __half*)p_hx;
    const __half* h0 = (const __half*)p_h0;
    const __half* h1 = (const __half*)p_h1;

    // bucket CSR build + x conversion
    cudaMemsetAsync(p_deg, 0, NN * sizeof(int));
    k_x2h<<<(NN * D / 4 + 255) / 256, 256>>>((const float4*)x);
    k_bucket<<<(NE / 4 + 255) / 256, 256>>>((const int4*)src, (const int4*)dst);

    const int agg_grid = (NN / 2 * 32 + 255) / 256;

    // layer 0: g_hx -> g_hh0
    k_gemm_dual_tc<<<GEMM_GRID, 512, GEMM_DSMEM>>>(hx, W1 + 0 * D * D, W2 + 0 * D * D);
    k_aggregate<<<agg_grid, 256>>>(0);
    // layer 1: g_hh0 -> g_hh1
    k_gemm_dual_tc<<<GEMM_GRID, 512, GEMM_DSMEM>>>(h0, W1 + 1 * D * D, W2 + 1 * D * D);
    k_aggregate<<<agg_grid, 256>>>(1);
    // layer 2: g_hh1 -> g_hh0
    k_gemm_dual_tc<<<GEMM_GRID, 512, GEMM_DSMEM>>>(h1, W1 + 2 * D * D, W2 + 2 * D * D);
    k_aggregate<<<agg_grid, 256>>>(0);

    k_pool<<<NG, 384>>>(batch);
    k_mlp<<<NG, 96>>>(cw1, cb1, cw2, cb2, out);
}

// round 14
// speedup vs baseline: 1.0162x; 1.0162x over previous
#include <cuda_runtime.h>
#include <cuda_fp16.h>
#include <cstdint>

#define NN 50000
#define NE 800000
#define D  96
#define NG 128
#define OD 10
#define CAP 96          // max in-degree bucket capacity (deg ~ Poisson(16))

// ---------------- scratch (static device globals; no allocation) ----------------
__device__ __align__(16) float  g_self[NN * D];
__device__ __align__(16) __half g_msg [NN * D];   // fp16 messages
__device__ __align__(16) __half g_hx  [NN * D];   // fp16 copy of x (layer-0 A)
__device__ __align__(16) __half g_hh0 [NN * D];   // fp16 hidden (ping)
__device__ __align__(16) __half g_hh1 [NN * D];   // fp16 hidden (pong)
__device__ int   g_deg [NN];
__device__ int   g_bkt [NN * CAP];
__device__ float g_emb [NG * D];

// ---------------- x -> fp16 conversion (once per launch) ----------------
__global__ void k_x2h(const float4* __restrict__ x4) {
    int i = blockIdx.x * blockDim.x + threadIdx.x;   // 4 floats per thread
    if (i < NN * D / 4) {
        float4 v = x4[i];
        __half2 p0 = __floats2half2_rn(v.x, v.y);
        __half2 p1 = __floats2half2_rn(v.z, v.w);
        *(uint2*)&g_hx[i * 4] = make_uint2(*(uint32_t*)&p0, *(uint32_t*)&p1);
    }
}

// ---------------- fused CSR bucket build: one pass over edges (R12-proven) ----------------
__global__ void k_bucket(const int* __restrict__ src, const int* __restrict__ dst) {
    int e = blockIdx.x * blockDim.x + threadIdx.x;
    if (e < NE) {
        int d = dst[e];
        int pos = atomicAdd(&g_deg[d], 1);
        if (pos < CAP) g_bkt[(size_t)d * CAP + pos] = src[e];
    }
}

// ---------------- fp16 MMA / async helpers ----------------
__device__ __forceinline__ void mma_f16(float* c,
                                        uint32_t a0, uint32_t a1, uint32_t a2, uint32_t a3,
                                        uint32_t b0, uint32_t b1) {
    asm volatile(
        "mma.sync.aligned.m16n8k16.row.col.f32.f16.f16.f32 "
        "{%0,%1,%2,%3}, {%4,%5,%6,%7}, {%8,%9}, {%0,%1,%2,%3};\n"
        : "+f"(c[0]), "+f"(c[1]), "+f"(c[2]), "+f"(c[3])
        : "r"(a0), "r"(a1), "r"(a2), "r"(a3), "r"(b0), "r"(b1));
}

__device__ __forceinline__ void cp16(uint32_t dst_smem, const void* src) {
    asm volatile("cp.async.ca.shared.global [%0], [%1], 16;\n" :: "r"(dst_smem), "l"(src));
}
__device__ __forceinline__ void cp_commit() {
    asm volatile("cp.async.commit_group;\n" ::: "memory");
}
template <int N>
__device__ __forceinline__ void cp_wait() {
    asm volatile("cp.async.wait_group %0;\n" :: "n"(N) : "memory");
}

// ---------------- persistent fused dual GEMM (fp16 tensor cores, fp32 accum) ---
// (unchanged — proven)
#define AH_STRIDE 52
#define ABUF_WORDS (128 * AH_STRIDE)                // 6656 words
#define SWH_WORDS  (48 * 96)                        // 4608 words per matrix
#define GEMM_DSMEM ((2 * ABUF_WORDS + 2 * SWH_WORDS) * 4)   // 88 KB
#define SW_XOR2(k2, n) ((n) ^ (((k2) & 3) * 8))
#define NTILES ((NN + 127) / 128)                   // 391
#define GEMM_GRID 148

__device__ __forceinline__ void stage_A(uint32_t abuf_addr, const __half* __restrict__ h,
                                        int row0, int t) {
#pragma unroll
    for (int i = 0; i < 3; i++) {
        int lin = t + i * 512;               // 0..1535
        int r = lin / 12;                    // 0..127
        int j = lin - r * 12;                // 0..11 (uint4 = 8 halves)
        int grow = row0 + r;
        if (grow >= NN) grow = NN - 1;       // clamp: masked at store
        cp16(abuf_addr + (r * AH_STRIDE + j * 4) * 4, h + (size_t)grow * D + j * 8);
    }
}

__global__ void __launch_bounds__(512, 1)
k_gemm_dual_tc(const __half* __restrict__ h,
               const float* __restrict__ W1, const float* __restrict__ W2) {
    extern __shared__ uint32_t smem[];
    uint32_t* sA = smem;                       // 2 x ABUF_WORDS (half2 words)
    uint32_t* sW = smem + 2 * ABUF_WORDS;      // 2 x [48][96] packed half2, xor-swizzled
    uint32_t sA_addr = (uint32_t)__cvta_generic_to_shared(sA);

    int t     = threadIdx.x;
    int warp  = t >> 5;
    int lane  = t & 31;
    int gq    = lane >> 2;
    int t4    = lane & 3;
    int warpM = warp >> 2;          // 0..3 -> rows [warpM*32, +32)
    int warpN = (warp >> 1) & 1;    // 0..1 -> cols [warpN*48, +48)
    int mat   = warp & 1;           // 0: W1/self, 1: W2/msg

    // ---- stage W1/W2 once: pack (k, k+1) pairs into half2, xor-swizzled ----
#pragma unroll
    for (int i = 0; i < 3; i++) {
        int idx = t + i * 512;               // 0..1535, need < 1152
        if (idx < 1152) {
            int k2 = idx / 24;               // 0..47
            int n4 = (idx - k2 * 24) * 4;    // 0..92
            const float* r0 = W1 + (2 * k2) * D + n4;
            float4 wa = *(const float4*)r0;
            float4 wb = *(const float4*)(r0 + D);
            __half2 p0 = __floats2half2_rn(wa.x, wb.x);
            __half2 p1 = __floats2half2_rn(wa.y, wb.y);
            __half2 p2 = __floats2half2_rn(wa.z, wb.z);
            __half2 p3 = __floats2half2_rn(wa.w, wb.w);
            int di = k2 * 96 + SW_XOR2(k2, n4);
            *(uint4*)&sW[di] = make_uint4(*(uint32_t*)&p0, *(uint32_t*)&p1,
                                          *(uint32_t*)&p2, *(uint32_t*)&p3);
            const float* q0 = W2 + (2 * k2) * D + n4;
            float4 va = *(const float4*)q0;
            float4 vb = *(const float4*)(q0 + D);
            __half2 u0 = __floats2half2_rn(va.x, vb.x);
            __half2 u1 = __floats2half2_rn(va.y, vb.y);
            __half2 u2 = __floats2half2_rn(va.z, vb.z);
            __half2 u3 = __floats2half2_rn(va.w, vb.w);
            *(uint4*)&sW[SWH_WORDS + di] = make_uint4(*(uint32_t*)&u0, *(uint32_t*)&u1,
                                                      *(uint32_t*)&u2, *(uint32_t*)&u3);
        }
    }

    const uint32_t* sWm = sW + mat * SWH_WORDS;

    int tile0 = blockIdx.x;
    if (tile0 >= NTILES) return;

    stage_A(sA_addr, h, tile0 * 128, t);
    cp_commit();

    int buf = 0;
    for (int tile = tile0; tile < NTILES; tile += GEMM_GRID) {
        int ntile = tile + GEMM_GRID;
        if (ntile >= NTILES) ntile = tile;
        stage_A(sA_addr + (buf ^ 1) * ABUF_WORDS * 4, h, ntile * 128, t);
        cp_commit();

        cp_wait<1>();
        __syncthreads();

        const uint32_t* A = sA + buf * ABUF_WORDS;
        float acc[2][6][4];
#pragma unroll
        for (int mt = 0; mt < 2; mt++)
#pragma unroll
            for (int nt = 0; nt < 6; nt++)
#pragma unroll
                for (int j = 0; j < 4; j++) acc[mt][nt][j] = 0.f;

#pragma unroll
        for (int ks = 0; ks < 6; ks++) {
            int k2b = ks * 8;
            uint32_t a0[2], a1[2], a2[2], a3[2];
#pragma unroll
            for (int mt = 0; mt < 2; mt++) {
                int r = warpM * 32 + mt * 16 + gq;
                int idx = r * AH_STRIDE + k2b + t4;
                a0[mt] = A[idx];
                a1[mt] = A[idx + 8 * AH_STRIDE];
                a2[mt] = A[idx + 4];
                a3[mt] = A[idx + 8 * AH_STRIDE + 4];
            }
#pragma unroll
            for (int nt = 0; nt < 6; nt++) {
                int n = warpN * 48 + nt * 8 + gq;
                int kb0 = k2b + t4;
                int kb1 = k2b + t4 + 4;
                uint32_t b0 = sWm[kb0 * 96 + SW_XOR2(kb0, n)];
                uint32_t b1 = sWm[kb1 * 96 + SW_XOR2(kb1, n)];
#pragma unroll
                for (int mt = 0; mt < 2; mt++)
                    mma_f16(acc[mt][nt], a0[mt], a1[mt], a2[mt], a3[mt], b0, b1);
            }
        }

        // epilogue: mat 0 -> g_self (fp32), mat 1 -> g_msg (fp16)
        int row0 = tile * 128;
#pragma unroll
        for (int mt = 0; mt < 2; mt++) {
            int row = row0 + warpM * 32 + mt * 16 + gq;
#pragma unroll
            for (int nt = 0; nt < 6; nt++) {
                int col = warpN * 48 + nt * 8 + 2 * t4;
                if (mat == 0) {
                    if (row < NN)
                        *(float2*)&g_self[row * D + col] = make_float2(acc[mt][nt][0], acc[mt][nt][1]);
                    if (row + 8 < NN)
                        *(float2*)&g_self[(row + 8) * D + col] = make_float2(acc[mt][nt][2], acc[mt][nt][3]);
                } else {
                    if (row < NN)
                        *(__half2*)&g_msg[row * D + col] =
                            __float22half2_rn(make_float2(acc[mt][nt][0], acc[mt][nt][1]));
                    if (row + 8 < NN)
                        *(__half2*)&g_msg[(row + 8) * D + col] =
                            __float22half2_rn(make_float2(acc[mt][nt][2], acc[mt][nt][3]));
                }
            }
        }
        __syncthreads();
        buf ^= 1;
    }
}

// ---------------- aggregation (proven floor shape: 32 regs, occ 77.7%) ----------------
__device__ __forceinline__ __half2 h2_(uint32_t u) { return *(__half2*)&u; }

__global__ void k_aggregate(int houtcode) {
    int gt   = blockIdx.x * blockDim.x + threadIdx.x;
    int warp = gt >> 5;
    int lane = gt & 31;
    int node = warp * 2 + (lane >> 4);
    int sub  = lane & 15;
    if (node >= NN || sub >= 12) return;

    const uint4* __restrict__ M = (const uint4*)g_msg;   // 12 uint4 per row
    float acc[8];
#pragma unroll
    for (int j = 0; j < 8; j++) acc[j] = 0.f;

    int deg = g_deg[node];
    if (deg > CAP) deg = CAP;
    const int* __restrict__ bkt = g_bkt + (size_t)node * CAP;

    int i = 0;
    for (; i + 2 <= deg; i += 2) {
        int s0 = bkt[i];
        int s1 = bkt[i + 1];
        uint4 ma = M[(size_t)s0 * 12 + sub];
        uint4 mb = M[(size_t)s1 * 12 + sub];
        __half2 p0 = __hadd2(h2_(ma.x), h2_(mb.x));
        __half2 p1 = __hadd2(h2_(ma.y), h2_(mb.y));
        __half2 p2 = __hadd2(h2_(ma.z), h2_(mb.z));
        __half2 p3 = __hadd2(h2_(ma.w), h2_(mb.w));
        float2 f0 = __half22float2(p0);
        float2 f1 = __half22float2(p1);
        float2 f2 = __half22float2(p2);
        float2 f3 = __half22float2(p3);
        acc[0] += f0.x; acc[1] += f0.y;
        acc[2] += f1.x; acc[3] += f1.y;
        acc[4] += f2.x; acc[5] += f2.y;
        acc[6] += f3.x; acc[7] += f3.y;
    }
    if (i < deg) {
        int s = bkt[i];
        uint4 mv = M[(size_t)s * 12 + sub];
        float2 f0 = __half22float2(h2_(mv.x));
        float2 f1 = __half22float2(h2_(mv.y));
        float2 f2 = __half22float2(h2_(mv.z));
        float2 f3 = __half22float2(h2_(mv.w));
        acc[0] += f0.x; acc[1] += f0.y;
        acc[2] += f1.x; acc[3] += f1.y;
        acc[4] += f2.x; acc[5] += f2.y;
        acc[6] += f3.x; acc[7] += f3.y;
    }

    const float4* __restrict__ S = (const float4*)(g_self + (size_t)node * D + sub * 8);
    float4 s0f = S[0];
    float4 s1f = S[1];
    __half* ho = ((houtcode == 0) ? g_hh0 : g_hh1) + (size_t)node * D + sub * 8;
    __half2 q0 = __floats2half2_rn(fmaxf(s0f.x + acc[0], 0.f), fmaxf(s0f.y + acc[1], 0.f));
    __half2 q1 = __floats2half2_rn(fmaxf(s0f.z + acc[2], 0.f), fmaxf(s0f.w + acc[3], 0.f));
    __half2 q2 = __floats2half2_rn(fmaxf(s1f.x + acc[4], 0.f), fmaxf(s1f.y + acc[5], 0.f));
    __half2 q3 = __floats2half2_rn(fmaxf(s1f.z + acc[6], 0.f), fmaxf(s1f.w + acc[7], 0.f));
    *(uint4*)ho = make_uint4(*(uint32_t*)&q0, *(uint32_t*)&q1,
                             *(uint32_t*)&q2, *(uint32_t*)&q3);
}

// ---------------- graph pooling (reads final fp16 h in g_hh0) ----------------
__device__ __forceinline__ int lowerb(const int* __restrict__ a, int n, int v) {
    int lo = 0, hi = n;
    while (lo < hi) {
        int mid = (lo + hi) >> 1;
        if (a[mid] < v) lo = mid + 1; else hi = mid;
    }
    return lo;
}

__global__ void k_pool(const int* __restrict__ batch) {
    __shared__ int   se[2];
    __shared__ float red[4][96];
    int g = blockIdx.x;
    int t = threadIdx.x;
    if (t == 0) se[0] = lowerb(batch, NN, g);
    if (t == 1) se[1] = lowerb(batch, NN, g + 1);
    __syncthreads();
    int d = t % 96;
    int q = t / 96;
    int s0 = se[0], s1 = se[1];
    float s = 0.f;
    for (int n = s0 + q; n < s1; n += 4) s += __half2float(g_hh0[(size_t)n * D + d]);
    red[q][d] = s;
    __syncthreads();
    if (q == 0) g_emb[g * D + d] = red[0][d] + red[1][d] + red[2][d] + red[3][d];
}

// ---------------- MLP head ----------------
__global__ void k_mlp(const float* __restrict__ cw1, const float* __restrict__ cb1,
                      const float* __restrict__ cw2, const float* __restrict__ cb2,
                      float* __restrict__ out) {
    __shared__ float emb[96];
    __shared__ float hid[96];
    int g = blockIdx.x;
    int d = threadIdx.x;  // 96 threads
    emb[d] = g_emb[g * D + d];
    __syncthreads();
    float s = cb1[d];
#pragma unroll 8
    for (int k = 0; k < 96; k++) s += emb[k] * cw1[k * D + d];
    hid[d] = fmaxf(s, 0.f);
    __syncthreads();
    if (d < OD) {
        float o = cb2[d];
#pragma unroll 8
        for (int k = 0; k < 96; k++) o += hid[k] * cw2[k * OD + d];
        out[g * OD + d] = o;
    }
}

// ---------------- launch ----------------
extern "C" void kernel_launch(void* const* d_in, const int* in_sizes, int n_in,
                              void* d_out, int out_size) {
    const float* x     = (const float*)d_in[0];
    const int*   ei    = (const int*)  d_in[1];
    const int*   batch = (const int*)  d_in[2];
    const float* W1    = (const float*)d_in[3];
    const float* W2    = (const float*)d_in[4];
    const float* cw1   = (const float*)d_in[5];
    const float* cb1   = (const float*)d_in[6];
    const float* cw2   = (const float*)d_in[7];
    const float* cb2   = (const float*)d_in[8];
    float* out = (float*)d_out;

    const int* src = ei;        // edge_index[0]
    const int* dst = ei + NE;   // edge_index[1]

    cudaFuncSetAttribute(k_gemm_dual_tc,
                         cudaFuncAttributeMaxDynamicSharedMemorySize, GEMM_DSMEM);

    void *p_deg = nullptr, *p_hx = nullptr, *p_h0 = nullptr, *p_h1 = nullptr;
    cudaGetSymbolAddress(&p_deg, g_deg);
    cudaGetSymbolAddress(&p_hx, g_hx);
    cudaGetSymbolAddress(&p_h0, g_hh0);
    cudaGetSymbolAddress(&p_h1, g_hh1);
    const __half* hx = (const __half*)p_hx;
    const __half* h0 = (const __half*)p_h0;
    const __half* h1 = (const __half*)p_h1;

    // lazily created side-stream + events (resources only; identical work per call)
    static cudaStream_t s_csr = nullptr;
    static cudaEvent_t  ev_fork = nullptr, ev_join = nullptr;
    if (s_csr == nullptr) {
        cudaStreamCreateWithFlags(&s_csr, cudaStreamNonBlocking);
        cudaEventCreateWithFlags(&ev_fork, cudaEventDisableTiming);
        cudaEventCreateWithFlags(&ev_join, cudaEventDisableTiming);
    }

    // fork: CSR build (memset + bucket) runs concurrently with x2h + layer-0 GEMM
    cudaEventRecord(ev_fork, 0);
    cudaStreamWaitEvent(s_csr, ev_fork, 0);
    cudaMemsetAsync(p_deg, 0, NN * sizeof(int), s_csr);
    k_bucket<<<(NE + 255) / 256, 256, 0, s_csr>>>(src, dst);
    cudaEventRecord(ev_join, s_csr);

    // main stream: x conversion + layer-0 GEMM (independent of CSR)
    k_x2h<<<(NN * D / 4 + 255) / 256, 256>>>((const float4*)x);
    k_gemm_dual_tc<<<GEMM_GRID, 512, GEMM_DSMEM>>>(hx, W1 + 0 * D * D, W2 + 0 * D * D);

    // join before first aggregate (needs buckets)
    cudaStreamWaitEvent(0, ev_join, 0);

    const int agg_grid = (NN / 2 * 32 + 255) / 256;

    k_aggregate<<<agg_grid, 256>>>(0);
    // layer 1: g_hh0 -> g_hh1
    k_gemm_dual_tc<<<GEMM_GRID, 512, GEMM_DSMEM>>>(h0, W1 + 1 * D * D, W2 + 1 * D * D);
    k_aggregate<<<agg_grid, 256>>>(1);
    // layer 2: g_hh1 -> g_hh0
    k_gemm_dual_tc<<<GEMM_GRID, 512, GEMM_DSMEM>>>(h1, W1 + 2 * D * D, W2 + 2 * D * D);
    k_aggregate<<<agg_grid, 256>>>(0);

    k_pool<<<NG, 384>>>(batch);
    k_mlp<<<NG, 96>>>(cw1, cb1, cw2, cb2, out);
}

// round 15
// speedup vs baseline: 1.0633x; 1.0463x over previous
#include <cuda_runtime.h>
#include <cuda_fp16.h>
#include <cstdint>

#define NN 50000
#define NE 800000
#define D  96
#define NG 128
#define OD 10
#define CAP 96          // max in-degree bucket capacity (deg ~ Poisson(16))

// ---------------- scratch (static device globals; no allocation) ----------------
__device__ __align__(16) float  g_self[NN * D];
__device__ __align__(16) __half g_msg [NN * D];   // fp16 messages
__device__ __align__(16) __half g_hx  [NN * D];   // fp16 copy of x (layer-0 A)
__device__ __align__(16) __half g_hh0 [NN * D];   // fp16 hidden (ping)
__device__ __align__(16) __half g_hh1 [NN * D];   // fp16 hidden (pong)
__device__ int   g_deg [NN];
__device__ int   g_bkt [NN * CAP];
__device__ float g_emb [NG * D];

// ---------------- x -> fp16 conversion (once per launch) ----------------
__global__ void k_x2h(const float4* __restrict__ x4) {
    int i = blockIdx.x * blockDim.x + threadIdx.x;   // 4 floats per thread
    if (i < NN * D / 4) {
        float4 v = x4[i];
        __half2 p0 = __floats2half2_rn(v.x, v.y);
        __half2 p1 = __floats2half2_rn(v.z, v.w);
        *(uint2*)&g_hx[i * 4] = make_uint2(*(uint32_t*)&p0, *(uint32_t*)&p1);
    }
}

// ---------------- fused CSR bucket build: one pass over edges (R12-proven) ----------------
__global__ void k_bucket(const int* __restrict__ src, const int* __restrict__ dst) {
    int e = blockIdx.x * blockDim.x + threadIdx.x;
    if (e < NE) {
        int d = dst[e];
        int pos = atomicAdd(&g_deg[d], 1);
        if (pos < CAP) g_bkt[(size_t)d * CAP + pos] = src[e];
    }
}

// ---------------- fp16 MMA / async helpers ----------------
__device__ __forceinline__ void mma_f16(float* c,
                                        uint32_t a0, uint32_t a1, uint32_t a2, uint32_t a3,
                                        uint32_t b0, uint32_t b1) {
    asm volatile(
        "mma.sync.aligned.m16n8k16.row.col.f32.f16.f16.f32 "
        "{%0,%1,%2,%3}, {%4,%5,%6,%7}, {%8,%9}, {%0,%1,%2,%3};\n"
        : "+f"(c[0]), "+f"(c[1]), "+f"(c[2]), "+f"(c[3])
        : "r"(a0), "r"(a1), "r"(a2), "r"(a3), "r"(b0), "r"(b1));
}

__device__ __forceinline__ void cp16(uint32_t dst_smem, const void* src) {
    asm volatile("cp.async.ca.shared.global [%0], [%1], 16;\n" :: "r"(dst_smem), "l"(src));
}
__device__ __forceinline__ void cp_commit() {
    asm volatile("cp.async.commit_group;\n" ::: "memory");
}
template <int N>
__device__ __forceinline__ void cp_wait() {
    asm volatile("cp.async.wait_group %0;\n" :: "n"(N) : "memory");
}

// ---------------- persistent fused dual GEMM (fp16 tensor cores, fp32 accum) ---
// (unchanged — proven)
#define AH_STRIDE 52
#define ABUF_WORDS (128 * AH_STRIDE)                // 6656 words
#define SWH_WORDS  (48 * 96)                        // 4608 words per matrix
#define GEMM_DSMEM ((2 * ABUF_WORDS + 2 * SWH_WORDS) * 4)   // 88 KB
#define SW_XOR2(k2, n) ((n) ^ (((k2) & 3) * 8))
#define NTILES ((NN + 127) / 128)                   // 391
#define GEMM_GRID 148

__device__ __forceinline__ void stage_A(uint32_t abuf_addr, const __half* __restrict__ h,
                                        int row0, int t) {
#pragma unroll
    for (int i = 0; i < 3; i++) {
        int lin = t + i * 512;               // 0..1535
        int r = lin / 12;                    // 0..127
        int j = lin - r * 12;                // 0..11 (uint4 = 8 halves)
        int grow = row0 + r;
        if (grow >= NN) grow = NN - 1;       // clamp: masked at store
        cp16(abuf_addr + (r * AH_STRIDE + j * 4) * 4, h + (size_t)grow * D + j * 8);
    }
}

__global__ void __launch_bounds__(512, 1)
k_gemm_dual_tc(const __half* __restrict__ h,
               const float* __restrict__ W1, const float* __restrict__ W2) {
    extern __shared__ uint32_t smem[];
    uint32_t* sA = smem;                       // 2 x ABUF_WORDS (half2 words)
    uint32_t* sW = smem + 2 * ABUF_WORDS;      // 2 x [48][96] packed half2, xor-swizzled
    uint32_t sA_addr = (uint32_t)__cvta_generic_to_shared(sA);

    int t     = threadIdx.x;
    int warp  = t >> 5;
    int lane  = t & 31;
    int gq    = lane >> 2;
    int t4    = lane & 3;
    int warpM = warp >> 2;          // 0..3 -> rows [warpM*32, +32)
    int warpN = (warp >> 1) & 1;    // 0..1 -> cols [warpN*48, +48)
    int mat   = warp & 1;           // 0: W1/self, 1: W2/msg

    // ---- stage W1/W2 once: pack (k, k+1) pairs into half2, xor-swizzled ----
#pragma unroll
    for (int i = 0; i < 3; i++) {
        int idx = t + i * 512;               // 0..1535, need < 1152
        if (idx < 1152) {
            int k2 = idx / 24;               // 0..47
            int n4 = (idx - k2 * 24) * 4;    // 0..92
            const float* r0 = W1 + (2 * k2) * D + n4;
            float4 wa = *(const float4*)r0;
            float4 wb = *(const float4*)(r0 + D);
            __half2 p0 = __floats2half2_rn(wa.x, wb.x);
            __half2 p1 = __floats2half2_rn(wa.y, wb.y);
            __half2 p2 = __floats2half2_rn(wa.z, wb.z);
            __half2 p3 = __floats2half2_rn(wa.w, wb.w);
            int di = k2 * 96 + SW_XOR2(k2, n4);
            *(uint4*)&sW[di] = make_uint4(*(uint32_t*)&p0, *(uint32_t*)&p1,
                                          *(uint32_t*)&p2, *(uint32_t*)&p3);
            const float* q0 = W2 + (2 * k2) * D + n4;
            float4 va = *(const float4*)q0;
            float4 vb = *(const float4*)(q0 + D);
            __half2 u0 = __floats2half2_rn(va.x, vb.x);
            __half2 u1 = __floats2half2_rn(va.y, vb.y);
            __half2 u2 = __floats2half2_rn(va.z, vb.z);
            __half2 u3 = __floats2half2_rn(va.w, vb.w);
            *(uint4*)&sW[SWH_WORDS + di] = make_uint4(*(uint32_t*)&u0, *(uint32_t*)&u1,
                                                      *(uint32_t*)&u2, *(uint32_t*)&u3);
        }
    }

    const uint32_t* sWm = sW + mat * SWH_WORDS;

    int tile0 = blockIdx.x;
    if (tile0 >= NTILES) return;

    stage_A(sA_addr, h, tile0 * 128, t);
    cp_commit();

    int buf = 0;
    for (int tile = tile0; tile < NTILES; tile += GEMM_GRID) {
        int ntile = tile + GEMM_GRID;
        if (ntile >= NTILES) ntile = tile;
        stage_A(sA_addr + (buf ^ 1) * ABUF_WORDS * 4, h, ntile * 128, t);
        cp_commit();

        cp_wait<1>();
        __syncthreads();

        const uint32_t* A = sA + buf * ABUF_WORDS;
        float acc[2][6][4];
#pragma unroll
        for (int mt = 0; mt < 2; mt++)
#pragma unroll
            for (int nt = 0; nt < 6; nt++)
#pragma unroll
                for (int j = 0; j < 4; j++) acc[mt][nt][j] = 0.f;

#pragma unroll
        for (int ks = 0; ks < 6; ks++) {
            int k2b = ks * 8;
            uint32_t a0[2], a1[2], a2[2], a3[2];
#pragma unroll
            for (int mt = 0; mt < 2; mt++) {
                int r = warpM * 32 + mt * 16 + gq;
                int idx = r * AH_STRIDE + k2b + t4;
                a0[mt] = A[idx];
                a1[mt] = A[idx + 8 * AH_STRIDE];
                a2[mt] = A[idx + 4];
                a3[mt] = A[idx + 8 * AH_STRIDE + 4];
            }
#pragma unroll
            for (int nt = 0; nt < 6; nt++) {
                int n = warpN * 48 + nt * 8 + gq;
                int kb0 = k2b + t4;
                int kb1 = k2b + t4 + 4;
                uint32_t b0 = sWm[kb0 * 96 + SW_XOR2(kb0, n)];
                uint32_t b1 = sWm[kb1 * 96 + SW_XOR2(kb1, n)];
#pragma unroll
                for (int mt = 0; mt < 2; mt++)
                    mma_f16(acc[mt][nt], a0[mt], a1[mt], a2[mt], a3[mt], b0, b1);
            }
        }

        // epilogue: mat 0 -> g_self (fp32), mat 1 -> g_msg (fp16)
        int row0 = tile * 128;
#pragma unroll
        for (int mt = 0; mt < 2; mt++) {
            int row = row0 + warpM * 32 + mt * 16 + gq;
#pragma unroll
            for (int nt = 0; nt < 6; nt++) {
                int col = warpN * 48 + nt * 8 + 2 * t4;
                if (mat == 0) {
                    if (row < NN)
                        *(float2*)&g_self[row * D + col] = make_float2(acc[mt][nt][0], acc[mt][nt][1]);
                    if (row + 8 < NN)
                        *(float2*)&g_self[(row + 8) * D + col] = make_float2(acc[mt][nt][2], acc[mt][nt][3]);
                } else {
                    if (row < NN)
                        *(__half2*)&g_msg[row * D + col] =
                            __float22half2_rn(make_float2(acc[mt][nt][0], acc[mt][nt][1]));
                    if (row + 8 < NN)
                        *(__half2*)&g_msg[(row + 8) * D + col] =
                            __float22half2_rn(make_float2(acc[mt][nt][2], acc[mt][nt][3]));
                }
            }
        }
        __syncthreads();
        buf ^= 1;
    }
}

// ---------------- aggregation: dense lane packing (all 32 lanes active) ----------------
// thread -> (node, sub): node = gt/12, sub = gt%12. Each 12-thread group covers one
// node's 96 dims (sub owns 8 dims = one uint4 of half2). Same pair-sum math as R10.
__device__ __forceinline__ __half2 h2_(uint32_t u) { return *(__half2*)&u; }

__global__ void k_aggregate(int houtcode) {
    int gt   = blockIdx.x * blockDim.x + threadIdx.x;
    int node = gt / 12;
    int sub  = gt - node * 12;
    if (node >= NN) return;

    const uint4* __restrict__ M = (const uint4*)g_msg;   // 12 uint4 per row
    float acc[8];
#pragma unroll
    for (int j = 0; j < 8; j++) acc[j] = 0.f;

    int deg = g_deg[node];
    if (deg > CAP) deg = CAP;
    const int* __restrict__ bkt = g_bkt + (size_t)node * CAP;

    int i = 0;
    for (; i + 2 <= deg; i += 2) {
        int s0 = bkt[i];
        int s1 = bkt[i + 1];
        uint4 ma = M[(size_t)s0 * 12 + sub];
        uint4 mb = M[(size_t)s1 * 12 + sub];
        __half2 p0 = __hadd2(h2_(ma.x), h2_(mb.x));
        __half2 p1 = __hadd2(h2_(ma.y), h2_(mb.y));
        __half2 p2 = __hadd2(h2_(ma.z), h2_(mb.z));
        __half2 p3 = __hadd2(h2_(ma.w), h2_(mb.w));
        float2 f0 = __half22float2(p0);
        float2 f1 = __half22float2(p1);
        float2 f2 = __half22float2(p2);
        float2 f3 = __half22float2(p3);
        acc[0] += f0.x; acc[1] += f0.y;
        acc[2] += f1.x; acc[3] += f1.y;
        acc[4] += f2.x; acc[5] += f2.y;
        acc[6] += f3.x; acc[7] += f3.y;
    }
    if (i < deg) {
        int s = bkt[i];
        uint4 mv = M[(size_t)s * 12 + sub];
        float2 f0 = __half22float2(h2_(mv.x));
        float2 f1 = __half22float2(h2_(mv.y));
        float2 f2 = __half22float2(h2_(mv.z));
        float2 f3 = __half22float2(h2_(mv.w));
        acc[0] += f0.x; acc[1] += f0.y;
        acc[2] += f1.x; acc[3] += f1.y;
        acc[4] += f2.x; acc[5] += f2.y;
        acc[6] += f3.x; acc[7] += f3.y;
    }

    const float4* __restrict__ S = (const float4*)(g_self + (size_t)node * D + sub * 8);
    float4 s0f = S[0];
    float4 s1f = S[1];
    __half* ho = ((houtcode == 0) ? g_hh0 : g_hh1) + (size_t)node * D + sub * 8;
    __half2 q0 = __floats2half2_rn(fmaxf(s0f.x + acc[0], 0.f), fmaxf(s0f.y + acc[1], 0.f));
    __half2 q1 = __floats2half2_rn(fmaxf(s0f.z + acc[2], 0.f), fmaxf(s0f.w + acc[3], 0.f));
    __half2 q2 = __floats2half2_rn(fmaxf(s1f.x + acc[4], 0.f), fmaxf(s1f.y + acc[5], 0.f));
    __half2 q3 = __floats2half2_rn(fmaxf(s1f.z + acc[6], 0.f), fmaxf(s1f.w + acc[7], 0.f));
    *(uint4*)ho = make_uint4(*(uint32_t*)&q0, *(uint32_t*)&q1,
                             *(uint32_t*)&q2, *(uint32_t*)&q3);
}

// ---------------- graph pooling (reads final fp16 h in g_hh0) ----------------
__device__ __forceinline__ int lowerb(const int* __restrict__ a, int n, int v) {
    int lo = 0, hi = n;
    while (lo < hi) {
        int mid = (lo + hi) >> 1;
        if (a[mid] < v) lo = mid + 1; else hi = mid;
    }
    return lo;
}

__global__ void k_pool(const int* __restrict__ batch) {
    __shared__ int   se[2];
    __shared__ float red[4][96];
    int g = blockIdx.x;
    int t = threadIdx.x;
    if (t == 0) se[0] = lowerb(batch, NN, g);
    if (t == 1) se[1] = lowerb(batch, NN, g + 1);
    __syncthreads();
    int d = t % 96;
    int q = t / 96;
    int s0 = se[0], s1 = se[1];
    float s = 0.f;
    for (int n = s0 + q; n < s1; n += 4) s += __half2float(g_hh0[(size_t)n * D + d]);
    red[q][d] = s;
    __syncthreads();
    if (q == 0) g_emb[g * D + d] = red[0][d] + red[1][d] + red[2][d] + red[3][d];
}

// ---------------- MLP head ----------------
__global__ void k_mlp(const float* __restrict__ cw1, const float* __restrict__ cb1,
                      const float* __restrict__ cw2, const float* __restrict__ cb2,
                      float* __restrict__ out) {
    __shared__ float emb[96];
    __shared__ float hid[96];
    int g = blockIdx.x;
    int d = threadIdx.x;  // 96 threads
    emb[d] = g_emb[g * D + d];
    __syncthreads();
    float s = cb1[d];
#pragma unroll 8
    for (int k = 0; k < 96; k++) s += emb[k] * cw1[k * D + d];
    hid[d] = fmaxf(s, 0.f);
    __syncthreads();
    if (d < OD) {
        float o = cb2[d];
#pragma unroll 8
        for (int k = 0; k < 96; k++) o += hid[k] * cw2[k * OD + d];
        out[g * OD + d] = o;
    }
}

// ---------------- launch ----------------
extern "C" void kernel_launch(void* const* d_in, const int* in_sizes, int n_in,
                              void* d_out, int out_size) {
    const float* x     = (const float*)d_in[0];
    const int*   ei    = (const int*)  d_in[1];
    const int*   batch = (const int*)  d_in[2];
    const float* W1    = (const float*)d_in[3];
    const float* W2    = (const float*)d_in[4];
    const float* cw1   = (const float*)d_in[5];
    const float* cb1   = (const float*)d_in[6];
    const float* cw2   = (const float*)d_in[7];
    const float* cb2   = (const float*)d_in[8];
    float* out = (float*)d_out;

    const int* src = ei;        // edge_index[0]
    const int* dst = ei + NE;   // edge_index[1]

    cudaFuncSetAttribute(k_gemm_dual_tc,
                         cudaFuncAttributeMaxDynamicSharedMemorySize, GEMM_DSMEM);

    void *p_deg = nullptr, *p_hx = nullptr, *p_h0 = nullptr, *p_h1 = nullptr;
    cudaGetSymbolAddress(&p_deg, g_deg);
    cudaGetSymbolAddress(&p_hx, g_hx);
    cudaGetSymbolAddress(&p_h0, g_hh0);
    cudaGetSymbolAddress(&p_h1, g_hh1);
    const __half* hx = (const __half*)p_hx;
    const __half* h0 = (const __half*)p_h0;
    const __half* h1 = (const __half*)p_h1;

    // lazily created side-stream + events (resources only; identical work per call)
    static cudaStream_t s_csr = nullptr;
    static cudaEvent_t  ev_fork = nullptr, ev_join = nullptr;
    if (s_csr == nullptr) {
        cudaStreamCreateWithFlags(&s_csr, cudaStreamNonBlocking);
        cudaEventCreateWithFlags(&ev_fork, cudaEventDisableTiming);
        cudaEventCreateWithFlags(&ev_join, cudaEventDisableTiming);
    }

    // fork: CSR build (memset + bucket) runs concurrently with x2h + layer-0 GEMM
    cudaEventRecord(ev_fork, 0);
    cudaStreamWaitEvent(s_csr, ev_fork, 0);
    cudaMemsetAsync(p_deg, 0, NN * sizeof(int), s_csr);
    k_bucket<<<(NE + 255) / 256, 256, 0, s_csr>>>(src, dst);
    cudaEventRecord(ev_join, s_csr);

    // main stream: x conversion + layer-0 GEMM (independent of CSR)
    k_x2h<<<(NN * D / 4 + 255) / 256, 256>>>((const float4*)x);
    k_gemm_dual_tc<<<GEMM_GRID, 512, GEMM_DSMEM>>>(hx, W1 + 0 * D * D, W2 + 0 * D * D);

    // join before first aggregate (needs buckets)
    cudaStreamWaitEvent(0, ev_join, 0);

    const int agg_grid = (NN * 12 + 255) / 256;

    k_aggregate<<<agg_grid, 256>>>(0);
    // layer 1: g_hh0 -> g_hh1
    k_gemm_dual_tc<<<GEMM_GRID, 512, GEMM_DSMEM>>>(h0, W1 + 1 * D * D, W2 + 1 * D * D);
    k_aggregate<<<agg_grid, 256>>>(1);
    // layer 2: g_hh1 -> g_hh0
    k_gemm_dual_tc<<<GEMM_GRID, 512, GEMM_DSMEM>>>(h1, W1 + 2 * D * D, W2 + 2 * D * D);
    k_aggregate<<<agg_grid, 256>>>(0);

    k_pool<<<NG, 384>>>(batch);
    k_mlp<<<NG, 96>>>(cw1, cb1, cw2, cb2, out);
}